// round 1
// baseline (speedup 1.0000x reference)
#include <cuda_runtime.h>
#include <cstdint>

// ============================================================================
// Fused ConvTranspose3d(32->64, k=5, s=2, p=2) + MaxPool(2) + MaxPool(3)
//   + channel-sum.
// Key facts:
//   * MaxPool(2) then MaxPool(3) with floor == MaxPool(k=6, stride=6) on y,
//     and every 6^3 window is fully in-bounds of y[31,63,63].
//   * Output cell (b, od', oh', ow') depends only on x[b, :, 3od'-1..3od'+3,
//     3oh'-1..+3, 3ow'-1..+3]  (5^3 patch per in-channel, -1 edge -> zero).
//   * For output pos o (parity p): taps k with k === o (mod 2);
//     local input index il = (r + 4 - k)/2 where r = o mod 6 window offset.
//     Even r: k in {4,2,0} (3 taps), odd r: k in {3,1} (2 taps, padded to 3
//     with a zero-weight slot kd=5).
// One CTA per output cell (8000 CTAs). 288 threads =
//   36 (rd,rh) window positions x 8 oc-tiles (8 channels each).
// Each thread: 6 w-positions x 8 oc packed-f32x2 accumulators in registers.
// Weights pre-transposed+padded to [ic][6][6][5][64] in a __device__ buffer,
// streamed into smem with a cp.async double buffer (2 ic per chunk).
// ============================================================================

#define THREADS 288
#define IC 32
#define OC 64
#define OCT 8
#define ICCH 2                       // in-channels per weight chunk
#define NCH (IC / ICCH)              // 16 chunks
#define WT_PER_IC (6 * 6 * 5 * OC)   // 11520 floats
#define WT_TOTAL (IC * WT_PER_IC)    // 368640 floats (1.47 MB)
#define CHUNK_FLOATS (ICCH * WT_PER_IC)  // 23040 floats (92160 B)
#define XS_FLOATS (IC * 6 * 6 * 8)   // 9216 floats (36864 B), padded tile
#define SMEM_FLOATS (XS_FLOATS + 2 * CHUNK_FLOATS)   // 55296
#define SMEM_BYTES (SMEM_FLOATS * 4) // 221184 B

__device__ __align__(16) float g_wt[WT_TOTAL];

// ---------------------------------------------------------------------------
// Weight transpose + zero-pad kernel:
//   g_wt[ic][kd(0..5)][kh(0..5)][kw(0..4)][oc] ; kd==5 or kh==5 -> 0
// from  w[ic][oc][kd][kh][kw]
// ---------------------------------------------------------------------------
__global__ void wt_transpose_kernel(const float* __restrict__ w) {
    int idx = blockIdx.x * blockDim.x + threadIdx.x;
    if (idx >= WT_TOTAL) return;
    int oc = idx & 63;
    int t  = idx >> 6;
    int kw = t % 5;  t /= 5;
    int kh = t % 6;  t /= 6;
    int kd = t % 6;
    int ic = t / 6;
    float v = 0.0f;
    if (kd < 5 && kh < 5)
        v = w[(((ic * OC + oc) * 5 + kd) * 5 + kh) * 5 + kw];
    g_wt[idx] = v;
}

// ---------------------------------------------------------------------------
// Packed fp32x2 helpers (Blackwell paired-FP32 pipe; only reachable via PTX)
// ---------------------------------------------------------------------------
__device__ __forceinline__ void ffma2(unsigned long long& a,
                                      unsigned long long xv,
                                      unsigned long long wv) {
    asm("fma.rn.f32x2 %0, %1, %2, %0;" : "+l"(a) : "l"(xv), "l"(wv));
}
__device__ __forceinline__ unsigned long long pack2(float v) {
    unsigned long long r;
    asm("mov.b64 %0, {%1, %1};" : "=l"(r) : "f"(v));
    return r;
}

__device__ __forceinline__ void cpa16(float* s, const float* g) {
    unsigned sa = (unsigned)__cvta_generic_to_shared(s);
    asm volatile("cp.async.cg.shared.global [%0], [%1], 16;" :: "r"(sa), "l"(g));
}
__device__ __forceinline__ void cp_commit() {
    asm volatile("cp.async.commit_group;");
}
__device__ __forceinline__ void cp_wait0() {
    asm volatile("cp.async.wait_group 0;");
}

// ---------------------------------------------------------------------------
// Main fused kernel. grid = (10 ow', 10 oh', 80 = b*5 + od'), block = 288.
// ---------------------------------------------------------------------------
extern __shared__ float smem_dyn[];

__global__ void __launch_bounds__(THREADS, 1)
fused_kernel(const float* __restrict__ x,
             const float* __restrict__ bias,
             float* __restrict__ out) {
    float* xs  = smem_dyn;                 // [32][6][6][8], zero-padded
    float* ws0 = smem_dyn + XS_FLOATS;     // double buffer, 2 x CHUNK_FLOATS

    const int owp = blockIdx.x;
    const int ohp = blockIdx.y;
    const int b   = blockIdx.z / 5;
    const int odp = blockIdx.z % 5;
    const int tid = threadIdx.x;

    // ---- stage 0: kick off weight chunk 0, zero the x tile ----
    for (int j = tid; j < CHUNK_FLOATS / 4; j += THREADS)
        cpa16(ws0 + 4 * j, g_wt + 4 * j);
    cp_commit();

    {
        float4 z4 = make_float4(0.f, 0.f, 0.f, 0.f);
        for (int i = tid; i < XS_FLOATS / 4; i += THREADS)
            ((float4*)xs)[i] = z4;
    }
    __syncthreads();   // zeroing done before real fills

    // ---- fill x patch: input idx range 3o'-1 .. 3o'+3 per dim ----
    {
        const int d0 = 3 * odp - 1, h0 = 3 * ohp - 1, w0 = 3 * owp - 1;
        for (int i = tid; i < IC * 125; i += THREADS) {
            int ic  = i / 125;
            int rem = i % 125;
            int ld = rem / 25, lh = (rem / 5) % 5, lw = rem % 5;
            int id = d0 + ld, ih = h0 + lh, iw = w0 + lw;
            if (id >= 0 && ih >= 0 && iw >= 0)  // upper bounds always in-range
                xs[((ic * 6 + ld) * 6 + lh) * 8 + lw] =
                    x[(((b * IC + ic) * 16 + id) * 32 + ih) * 32 + iw];
        }
    }
    cp_wait0();
    __syncthreads();   // chunk 0 + x tile ready

    // ---- per-thread geometry ----
    const int posid = tid >> 3;        // 0..35
    const int ocb   = (tid & 7) * OCT; // oc base 0..56
    const int rd = posid / 6, rh = posid % 6;
    const int bd = (rd + 1) >> 1, bh = (rh + 1) >> 1;
    const bool de = (rd & 1) == 0, he = (rh & 1) == 0;
    // tap slot indices into padded weight (slot 5 == zeros)
    const int kds_[3] = { de ? 4 : 3, de ? 2 : 1, de ? 0 : 5 };
    const int khs_[3] = { he ? 4 : 3, he ? 2 : 1, he ? 0 : 5 };

    unsigned long long acc[6][4];
    #pragma unroll
    for (int r = 0; r < 6; r++)
        #pragma unroll
        for (int q = 0; q < 4; q++)
            acc[r][q] = 0ull;

    // ---- main loop: 16 chunks of 2 in-channels, double-buffered ----
    for (int c = 0; c < NCH; c++) {
        const float* cur = ws0 + (c & 1) * CHUNK_FLOATS;
        if (c + 1 < NCH) {
            float* nxt = ws0 + ((c + 1) & 1) * CHUNK_FLOATS;
            const float* src = g_wt + (c + 1) * CHUNK_FLOATS;
            for (int j = tid; j < CHUNK_FLOATS / 4; j += THREADS)
                cpa16(nxt + 4 * j, src + 4 * j);
        }
        cp_commit();

        #pragma unroll
        for (int icloc = 0; icloc < ICCH; icloc++) {
            const int ic = c * ICCH + icloc;
            #pragma unroll
            for (int jd = 0; jd < 3; jd++) {
                const int kds = kds_[jd];
                const int ild = bd + jd;          // <= 5 (pad row is zero)
                #pragma unroll
                for (int jh = 0; jh < 3; jh++) {
                    const int khs = khs_[jh];
                    const int ilh = bh + jh;
                    const float* xr = xs + ((ic * 6 + ild) * 6 + ilh) * 8;
                    float4 xa = *(const float4*)xr;
                    float  x4v = xr[4];
                    unsigned long long xp[5];
                    xp[0] = pack2(xa.x); xp[1] = pack2(xa.y);
                    xp[2] = pack2(xa.z); xp[3] = pack2(xa.w);
                    xp[4] = pack2(x4v);
                    const float* wbase =
                        cur + (((icloc * 6 + kds) * 6 + khs) * 5) * OC + ocb;
                    #pragma unroll
                    for (int kw = 0; kw < 5; kw++) {
                        const int bw = (4 - kw + (kw & 1)) >> 1; // 2,2,1,1,0
                        const float* wp = wbase + kw * OC;
                        ulonglong2 wA = *(const ulonglong2*)wp;        // oc+0..3
                        ulonglong2 wB = *(const ulonglong2*)(wp + 4);  // oc+4..7
                        #pragma unroll
                        for (int t = 0; t < 3; t++) {
                            const int r = (kw & 1) + 2 * t;  // w-position
                            unsigned long long xv = xp[bw + t];
                            ffma2(acc[r][0], xv, wA.x);
                            ffma2(acc[r][1], xv, wA.y);
                            ffma2(acc[r][2], xv, wB.x);
                            ffma2(acc[r][3], xv, wB.y);
                        }
                    }
                }
            }
        }
        cp_wait0();
        __syncthreads();
    }

    // ---- reduction: per-oc max over 216 positions, +bias, sum over oc ----
    __syncthreads();               // done reading xs; reuse it as scratch
    float* red = xs;               // [36][64] partial maxes, then [64] at 2304

    #pragma unroll
    for (int q = 0; q < 4; q++) {
        float mlo = -3.4e38f, mhi = -3.4e38f;
        #pragma unroll
        for (int r = 0; r < 6; r++) {
            unsigned long long a = acc[r][q];
            float lo = __uint_as_float((unsigned)(a & 0xffffffffu));
            float hi = __uint_as_float((unsigned)(a >> 32));
            mlo = fmaxf(mlo, lo);
            mhi = fmaxf(mhi, hi);
        }
        red[posid * 64 + ocb + 2 * q]     = mlo;
        red[posid * 64 + ocb + 2 * q + 1] = mhi;
    }
    __syncthreads();

    if (tid < 64) {
        float v = -3.4e38f;
        #pragma unroll 4
        for (int p = 0; p < 36; p++)
            v = fmaxf(v, red[p * 64 + tid]);
        red[36 * 64 + tid] = v + bias[tid];
    }
    __syncthreads();

    if (tid == 0) {
        float s = 0.0f;
        #pragma unroll 8
        for (int o = 0; o < 64; o++)
            s += red[36 * 64 + o];
        out[((b * 5 + odp) * 10 + ohp) * 10 + owp] = s;
    }
}

// ---------------------------------------------------------------------------
extern "C" void kernel_launch(void* const* d_in, const int* in_sizes, int n_in,
                              void* d_out, int out_size) {
    const float* x    = (const float*)d_in[0];   // [16,32,16,32,32]
    const float* w    = (const float*)d_in[1];   // [32,64,5,5,5]
    const float* bias = (const float*)d_in[2];   // [64]
    float* out = (float*)d_out;                  // [16,1,5,10,10] = 8000

    wt_transpose_kernel<<<(WT_TOTAL + 255) / 256, 256>>>(w);

    cudaFuncSetAttribute(fused_kernel,
                         cudaFuncAttributeMaxDynamicSharedMemorySize,
                         SMEM_BYTES);
    dim3 grid(10, 10, 80);   // (ow', oh', b*5 + od')
    fused_kernel<<<grid, THREADS, SMEM_BYTES>>>(x, bias, out);
}

// round 3
// speedup vs baseline: 2.5784x; 2.5784x over previous
#include <cuda_runtime.h>
#include <cstdint>

// ============================================================================
// Fused ConvTranspose3d(32->64,k=5,s=2,p=2) + MaxPool(2) + MaxPool(3) + ch-sum
// == MaxPool(k=6,s=6) on y then sum. One CTA computes 2 adjacent w'-cells.
//
// Geometry: y pos o (per dim) uses taps k === o (mod 2); local input index
// il = (r + 4 - k)/2 (r = offset within the pooled window / cell pair).
// All rd of one parity share the same kd tap set -> a thread accumulates
// 3 rd positions x 12 w-positions (2 cells) reusing each weight 18x.
//
// Block: 384 threads = 12 warps. warp <-> (rd-parity p, rh), lane <-> oc pair
// (f32x2). Warp classes have 9/6/6/4 (kd,kh) iterations; the wid->(p,rh)
// table permutes classes so each SMSP (wid&3) gets balanced work.
// Weights compacted to [ic][kd5][kh5][kw5][oc64] and streamed through a
// 2-ic cp.async double buffer. x patch stored duplicated {v,v} for direct
// f32x2 broadcast loads.
// ============================================================================

#define THREADS 384
#define IC 32
#define OC 64
#define WT_PER_IC (125 * OC)             // 8000 floats
#define WT_TOTAL (IC * WT_PER_IC)        // 256000 floats (1.02 MB)
#define ICCH 2
#define NCH (IC / ICCH)                  // 16 chunks
#define CHUNK_FLOATS (ICCH * WT_PER_IC)  // 16000 floats (64 KB)
#define XS_FLOATS (IC * 5 * 5 * 8 * 2)   // 12800 floats (51.2 KB, duplicated)
#define SMEM_FLOATS (XS_FLOATS + 2 * CHUNK_FLOATS)   // 44800
#define SMEM_BYTES (SMEM_FLOATS * 4)     // 179200 B

__device__ __align__(16) float g_wt[WT_TOTAL];

// g_wt[ic][kd][kh][kw][oc]  <-  w[ic][oc][kd][kh][kw]
__global__ void wt_transpose_kernel(const float* __restrict__ w) {
    int idx = blockIdx.x * blockDim.x + threadIdx.x;
    if (idx >= WT_TOTAL) return;
    int oc = idx & 63;
    int t  = idx >> 6;
    int kw = t % 5;  t /= 5;
    int kh = t % 5;  t /= 5;
    int kd = t % 5;
    int ic = t / 5;
    g_wt[idx] = w[(((ic * OC + oc) * 5 + kd) * 5 + kh) * 5 + kw];
}

typedef unsigned long long ull;

__device__ __forceinline__ void ffma2(ull& a, ull xv, ull wv) {
    asm("fma.rn.f32x2 %0, %1, %2, %0;" : "+l"(a) : "l"(xv), "l"(wv));
}
__device__ __forceinline__ void cpa16(float* s, const float* g) {
    unsigned sa = (unsigned)__cvta_generic_to_shared(s);
    asm volatile("cp.async.cg.shared.global [%0], [%1], 16;" :: "r"(sa), "l"(g));
}
__device__ __forceinline__ void cp_commit() {
    asm volatile("cp.async.commit_group;");
}
__device__ __forceinline__ void cp_wait0() {
    asm volatile("cp.async.wait_group 0;");
}
__device__ __forceinline__ float alo(ull a) {
    return __uint_as_float((unsigned)(a & 0xffffffffull));
}
__device__ __forceinline__ float ahi(ull a) {
    return __uint_as_float((unsigned)(a >> 32));
}

extern __shared__ float smem_dyn[];

// wid -> (p, rh) permuted so SMSP (wid&3) class-sums are {9,6,4}*3 + {6,6,6}
__device__ __constant__ int c_p[12]  = {0,0,0, 0, 1,1,1, 0, 1,1,1, 0};
__device__ __constant__ int c_rh[12] = {0,2,4, 1, 0,2,4, 3, 1,3,5, 5};

__global__ void __launch_bounds__(THREADS, 1)
fused_kernel(const float* __restrict__ x,
             const float* __restrict__ bias,
             float* __restrict__ out) {
    float* xs  = smem_dyn;                // duplicated x tile [32][5][5][8]x2
    float* ws0 = smem_dyn + XS_FLOATS;    // weight double buffer

    const int px  = blockIdx.x;           // w'-pair: cells 2px, 2px+1
    const int ohp = blockIdx.y;
    const int b   = blockIdx.z / 5;
    const int odp = blockIdx.z % 5;
    const int tid = threadIdx.x;

    // ---- stage chunk 0 ----
    for (int j = tid; j < CHUNK_FLOATS / 4; j += THREADS)
        cpa16(ws0 + 4 * j, g_wt + 4 * j);
    cp_commit();

    // ---- fill x patch (zero at id/ih/iw == -1; upper bounds always ok) ----
    {
        const int d0 = 3 * odp - 1, h0 = 3 * ohp - 1, w0 = 6 * px - 1;
        for (int i = tid; i < IC * 200; i += THREADS) {
            int ic  = i / 200;
            int rem = i % 200;
            int ild = rem / 40;
            int ilh = (rem / 8) % 5;
            int ilw = rem % 8;
            int id = d0 + ild, ih = h0 + ilh, iw = w0 + ilw;
            float v = 0.0f;
            if (id >= 0 && ih >= 0 && iw >= 0)
                v = x[(((b * IC + ic) * 16 + id) * 32 + ih) * 32 + iw];
            ((float2*)xs)[i] = make_float2(v, v);
        }
    }
    cp_wait0();
    __syncthreads();

    // ---- warp geometry ----
    const int wid  = tid >> 5;
    const int lane = tid & 31;
    const int p  = c_p[wid];        // rd parity: rd = p + 2*rd_i
    const int rh = c_rh[wid];
    const int ph = rh & 1;
    const int q  = rh >> 1;
    const int ntd = 3 - p;          // # kd taps (kd = p + 2*jd)
    const int nth = 3 - ph;         // # kh taps (kh = ph + 2*jh)

    ull acc[3][12];
    #pragma unroll
    for (int ri = 0; ri < 3; ri++)
        #pragma unroll
        for (int r = 0; r < 12; r++)
            acc[ri][r] = 0ull;

    // ---- main loop: 16 chunks of 2 in-channels ----
    for (int c = 0; c < NCH; c++) {
        const float* cur = ws0 + (c & 1) * CHUNK_FLOATS;
        if (c + 1 < NCH) {
            float* nxt = ws0 + ((c + 1) & 1) * CHUNK_FLOATS;
            const float* src = g_wt + (c + 1) * CHUNK_FLOATS;
            for (int j = tid; j < CHUNK_FLOATS / 4; j += THREADS)
                cpa16(nxt + 4 * j, src + 4 * j);
        }
        cp_commit();

        #pragma unroll
        for (int icl = 0; icl < ICCH; icl++) {
            const int ic = c * ICCH + icl;
            const float* wic = cur + icl * WT_PER_IC;
            const float* xic = xs + ic * 400;        // 5*5*8*2

            for (int jd = 0; jd < ntd; ++jd) {
                const int kd = p + 2 * jd;
                for (int jh = 0; jh < nth; ++jh) {
                    const int kh = ph + 2 * jh;
                    const int ilh = q + 2 - jh;
                    const float* wp = wic + (kd * 5 + kh) * 5 * OC + 2 * lane;
                    ull wv[5];
                    #pragma unroll
                    for (int kw = 0; kw < 5; kw++)
                        wv[kw] = *(const ull*)(wp + kw * OC);

                    #pragma unroll
                    for (int ri = 0; ri < 3; ri++) {
                        const int ild = ri + 2 - jd;           // 0..4
                        const float* xr = xic + (ild * 5 + ilh) * 16;
                        ull xp[8];
                        #pragma unroll
                        for (int jj = 0; jj < 4; jj++) {
                            ulonglong2 t2 = ((const ulonglong2*)xr)[jj];
                            xp[2 * jj]     = t2.x;
                            xp[2 * jj + 1] = t2.y;
                        }
                        #pragma unroll
                        for (int kw = 0; kw < 5; kw++) {
                            const int bw = (4 - kw + (kw & 1)) >> 1; // 2,2,1,1,0
                            #pragma unroll
                            for (int j = 0; j < 6; j++)
                                ffma2(acc[ri][(kw & 1) + 2 * j],
                                      xp[j + bw], wv[kw]);
                        }
                    }
                }
            }
        }
        cp_wait0();
        __syncthreads();
    }

    // ---- reduction: partial max per (warp-class, cell, oc) ----
    float* red = smem_dyn;     // reuse: [12][2][64] + 4 scratch
    #pragma unroll
    for (int cell = 0; cell < 2; cell++) {
        float mlo = -3.4e38f, mhi = -3.4e38f;
        #pragma unroll
        for (int ri = 0; ri < 3; ri++)
            #pragma unroll
            for (int jr = 0; jr < 6; jr++) {
                ull a = acc[ri][cell * 6 + jr];
                mlo = fmaxf(mlo, alo(a));
                mhi = fmaxf(mhi, ahi(a));
            }
        red[(wid * 2 + cell) * OC + 2 * lane]     = mlo;
        red[(wid * 2 + cell) * OC + 2 * lane + 1] = mhi;
    }
    __syncthreads();

    if (tid < 128) {
        const int cell = tid >> 6;
        const int oc   = tid & 63;
        float v = red[cell * OC + oc];
        #pragma unroll
        for (int w = 1; w < 12; w++)
            v = fmaxf(v, red[(w * 2 + cell) * OC + oc]);
        v += bias[oc];
        #pragma unroll
        for (int off = 16; off > 0; off >>= 1)
            v += __shfl_xor_sync(0xffffffffu, v, off);
        if ((tid & 31) == 0)
            red[1536 + (tid >> 5)] = v;   // 2 partials per cell
    }
    __syncthreads();

    if (tid < 2) {
        float s = red[1536 + 2 * tid] + red[1536 + 2 * tid + 1];
        out[((b * 5 + odp) * 10 + ohp) * 10 + 2 * px + tid] = s;
    }
}

// ---------------------------------------------------------------------------
extern "C" void kernel_launch(void* const* d_in, const int* in_sizes, int n_in,
                              void* d_out, int out_size) {
    const float* x    = (const float*)d_in[0];   // [16,32,16,32,32]
    const float* w    = (const float*)d_in[1];   // [32,64,5,5,5]
    const float* bias = (const float*)d_in[2];   // [64]
    float* out = (float*)d_out;                  // 8000

    wt_transpose_kernel<<<(WT_TOTAL + 255) / 256, 256>>>(w);

    cudaFuncSetAttribute(fused_kernel,
                         cudaFuncAttributeMaxDynamicSharedMemorySize,
                         SMEM_BYTES);
    dim3 grid(5, 10, 80);   // (w'-pair, oh', b*5 + od')
    fused_kernel<<<grid, THREADS, SMEM_BYTES>>>(x, bias, out);
}

// round 5
// speedup vs baseline: 2.7706x; 1.0745x over previous
#include <cuda_runtime.h>
#include <cstdint>

// ============================================================================
// Fused ConvTranspose3d(32->64,k=5,s=2,p=2) + MaxPool(2) + MaxPool(3) + ch-sum
// == MaxPool(k=6,s=6) on y then sum. One CTA computes 2 adjacent w'-cells.
//
// R5 (= R4 resubmit after infra failure): per-ic body specialized on warp
// parity class via template<P,PH> with full unroll -> immediate smem
// addressing, x-row loads hoisted (each row feeds up to 90 ffma2), long
// straight-line body for latency hiding.
// ============================================================================

#define THREADS 384
#define IC 32
#define OC 64
#define WT_PER_IC (125 * OC)             // 8000 floats
#define WT_TOTAL (IC * WT_PER_IC)        // 256000 floats (1.02 MB)
#define ICCH 2
#define NCH (IC / ICCH)                  // 16 chunks
#define CHUNK_FLOATS (ICCH * WT_PER_IC)  // 16000 floats (64 KB)
#define XS_FLOATS (IC * 5 * 5 * 8 * 2)   // 12800 floats (51.2 KB, duplicated)
#define SMEM_FLOATS (XS_FLOATS + 2 * CHUNK_FLOATS)   // 44800
#define SMEM_BYTES (SMEM_FLOATS * 4)     // 179200 B

__device__ __align__(16) float g_wt[WT_TOTAL];

// g_wt[ic][kd][kh][kw][oc]  <-  w[ic][oc][kd][kh][kw]
__global__ void wt_transpose_kernel(const float* __restrict__ w) {
    int idx = blockIdx.x * blockDim.x + threadIdx.x;
    if (idx >= WT_TOTAL) return;
    int oc = idx & 63;
    int t  = idx >> 6;
    int kw = t % 5;  t /= 5;
    int kh = t % 5;  t /= 5;
    int kd = t % 5;
    int ic = t / 5;
    g_wt[idx] = w[(((ic * OC + oc) * 5 + kd) * 5 + kh) * 5 + kw];
}

typedef unsigned long long ull;

__device__ __forceinline__ void ffma2(ull& a, ull xv, ull wv) {
    asm("fma.rn.f32x2 %0, %1, %2, %0;" : "+l"(a) : "l"(xv), "l"(wv));
}
__device__ __forceinline__ void cpa16(float* s, const float* g) {
    unsigned sa = (unsigned)__cvta_generic_to_shared(s);
    asm volatile("cp.async.cg.shared.global [%0], [%1], 16;" :: "r"(sa), "l"(g));
}
__device__ __forceinline__ void cp_commit() {
    asm volatile("cp.async.commit_group;");
}
__device__ __forceinline__ void cp_wait0() {
    asm volatile("cp.async.wait_group 0;" ::: "memory");
}
__device__ __forceinline__ float alo(ull a) {
    return __uint_as_float((unsigned)(a & 0xffffffffull));
}
__device__ __forceinline__ float ahi(ull a) {
    return __uint_as_float((unsigned)(a >> 32));
}

// ---------------------------------------------------------------------------
// Per-in-channel compute body, specialized on rd-parity P and rh-parity PH.
// wic_l: weight base for this ic (incl. +2*lane oc offset)
// xq:    xs + ic*400 + q*16   (q = rh>>1)
// ---------------------------------------------------------------------------
template<int P, int PH>
__device__ __forceinline__ void compute_ic(const float* __restrict__ wic_l,
                                           const float* __restrict__ xq,
                                           ull (&acc)[3][12]) {
    #pragma unroll
    for (int jh = 0; jh < 3 - PH; jh++) {
        const int kh = PH + 2 * jh;
        // weight tap block: all kd of this parity x 5 kw (immediate offsets)
        ull wv[3][5];
        #pragma unroll
        for (int jd = 0; jd < 3 - P; jd++) {
            const int kd = P + 2 * jd;
            #pragma unroll
            for (int kw = 0; kw < 5; kw++)
                wv[jd][kw] =
                    *(const ull*)(wic_l + (((kd * 5 + kh) * 5 + kw) << 6));
        }
        // x rows: ild in [P..4]; each row loaded once, reused across jd
        #pragma unroll
        for (int ild = P; ild < 5; ild++) {
            const float* xr = xq + ild * 80 + (2 - jh) * 16;
            ull xp[8];
            #pragma unroll
            for (int jj = 0; jj < 4; jj++) {
                ulonglong2 t2 = ((const ulonglong2*)xr)[jj];
                xp[2 * jj]     = t2.x;
                xp[2 * jj + 1] = t2.y;
            }
            #pragma unroll
            for (int jd = 0; jd < 3 - P; jd++) {
                const int ri = ild - 2 + jd;      // rd tile index
                if (ri < 0 || ri > 2) continue;   // compile-time pruned
                #pragma unroll
                for (int kw = 0; kw < 5; kw++) {
                    const int bw = (4 - kw + (kw & 1)) >> 1; // 2,2,1,1,0
                    #pragma unroll
                    for (int j = 0; j < 6; j++)
                        ffma2(acc[ri][(kw & 1) + 2 * j], xp[j + bw],
                              wv[jd][kw]);
                }
            }
        }
    }
}

extern __shared__ float smem_dyn[];

// wid -> (p, rh) permuted so SMSP (wid&3) class-sums are {9,6,4}*3 + {6,6,6}
__device__ __constant__ int c_p[12]  = {0,0,0, 0, 1,1,1, 0, 1,1,1, 0};
__device__ __constant__ int c_rh[12] = {0,2,4, 1, 0,2,4, 3, 1,3,5, 5};

__global__ void __launch_bounds__(THREADS, 1)
fused_kernel(const float* __restrict__ x,
             const float* __restrict__ bias,
             float* __restrict__ out) {
    float* xs  = smem_dyn;                // duplicated x tile [32][5][5][8]x2
    float* ws0 = smem_dyn + XS_FLOATS;    // weight double buffer

    const int px  = blockIdx.x;           // w'-pair: cells 2px, 2px+1
    const int ohp = blockIdx.y;
    const int b   = blockIdx.z / 5;
    const int odp = blockIdx.z % 5;
    const int tid = threadIdx.x;

    // ---- stage chunk 0 ----
    for (int j = tid; j < CHUNK_FLOATS / 4; j += THREADS)
        cpa16(ws0 + 4 * j, g_wt + 4 * j);
    cp_commit();

    // ---- fill x patch (zero at id/ih/iw == -1; upper bounds always ok) ----
    {
        const int d0 = 3 * odp - 1, h0 = 3 * ohp - 1, w0 = 6 * px - 1;
        for (int i = tid; i < IC * 200; i += THREADS) {
            int ic  = i / 200;
            int rem = i % 200;
            int ild = rem / 40;
            int ilh = (rem / 8) % 5;
            int ilw = rem % 8;
            int id = d0 + ild, ih = h0 + ilh, iw = w0 + ilw;
            float v = 0.0f;
            if (id >= 0 && ih >= 0 && iw >= 0)
                v = x[(((b * IC + ic) * 16 + id) * 32 + ih) * 32 + iw];
            ((float2*)xs)[i] = make_float2(v, v);
        }
    }
    cp_wait0();
    __syncthreads();

    // ---- warp geometry ----
    const int wid  = tid >> 5;
    const int lane = tid & 31;
    const int p  = c_p[wid];        // rd parity
    const int rh = c_rh[wid];
    const int ph = rh & 1;
    const int q  = rh >> 1;

    ull acc[3][12];
    #pragma unroll
    for (int ri = 0; ri < 3; ri++)
        #pragma unroll
        for (int r = 0; r < 12; r++)
            acc[ri][r] = 0ull;

    // ---- main loop: 16 chunks of 2 in-channels ----
    for (int c = 0; c < NCH; c++) {
        const float* cur = ws0 + (c & 1) * CHUNK_FLOATS;
        if (c + 1 < NCH) {
            float* nxt = ws0 + ((c + 1) & 1) * CHUNK_FLOATS;
            const float* src = g_wt + (c + 1) * CHUNK_FLOATS;
            for (int j = tid; j < CHUNK_FLOATS / 4; j += THREADS)
                cpa16(nxt + 4 * j, src + 4 * j);
        }
        cp_commit();

        #pragma unroll 1
        for (int icl = 0; icl < ICCH; icl++) {
            const int ic = c * ICCH + icl;
            const float* wic_l = cur + icl * WT_PER_IC + 2 * lane;
            const float* xq    = xs + ic * 400 + q * 16;
            if (p == 0) {
                if (ph == 0) compute_ic<0, 0>(wic_l, xq, acc);
                else         compute_ic<0, 1>(wic_l, xq, acc);
            } else {
                if (ph == 0) compute_ic<1, 0>(wic_l, xq, acc);
                else         compute_ic<1, 1>(wic_l, xq, acc);
            }
        }
        cp_wait0();
        __syncthreads();
    }

    // ---- reduction: partial max per (warp-class, cell, oc) ----
    float* red = smem_dyn;     // reuse: [12][2][64] + scratch
    #pragma unroll
    for (int cell = 0; cell < 2; cell++) {
        float mlo = -3.4e38f, mhi = -3.4e38f;
        #pragma unroll
        for (int ri = 0; ri < 3; ri++)
            #pragma unroll
            for (int jr = 0; jr < 6; jr++) {
                ull a = acc[ri][cell * 6 + jr];
                mlo = fmaxf(mlo, alo(a));
                mhi = fmaxf(mhi, ahi(a));
            }
        red[(wid * 2 + cell) * OC + 2 * lane]     = mlo;
        red[(wid * 2 + cell) * OC + 2 * lane + 1] = mhi;
    }
    __syncthreads();

    if (tid < 128) {
        const int cell = tid >> 6;
        const int oc   = tid & 63;
        float v = red[cell * OC + oc];
        #pragma unroll
        for (int w = 1; w < 12; w++)
            v = fmaxf(v, red[(w * 2 + cell) * OC + oc]);
        v += bias[oc];
        #pragma unroll
        for (int off = 16; off > 0; off >>= 1)
            v += __shfl_xor_sync(0xffffffffu, v, off);
        if ((tid & 31) == 0)
            red[1536 + (tid >> 5)] = v;   // 2 partials per cell
    }
    __syncthreads();

    if (tid < 2) {
        float s = red[1536 + 2 * tid] + red[1536 + 2 * tid + 1];
        out[((b * 5 + odp) * 10 + ohp) * 10 + 2 * px + tid] = s;
    }
}

// ---------------------------------------------------------------------------
extern "C" void kernel_launch(void* const* d_in, const int* in_sizes, int n_in,
                              void* d_out, int out_size) {
    const float* x    = (const float*)d_in[0];   // [16,32,16,32,32]
    const float* w    = (const float*)d_in[1];   // [32,64,5,5,5]
    const float* bias = (const float*)d_in[2];   // [64]
    float* out = (float*)d_out;                  // 8000

    wt_transpose_kernel<<<(WT_TOTAL + 255) / 256, 256>>>(w);

    cudaFuncSetAttribute(fused_kernel,
                         cudaFuncAttributeMaxDynamicSharedMemorySize,
                         SMEM_BYTES);
    dim3 grid(5, 10, 80);   // (w'-pair, oh', b*5 + od')
    fused_kernel<<<grid, THREADS, SMEM_BYTES>>>(x, bias, out);
}